// round 12
// baseline (speedup 1.0000x reference)
#include <cuda_runtime.h>
#include <cuda_fp16.h>
#include <cstdint>
#include <cstddef>

// ----------------------------------------------------------------------------
// ForecastNetSimple via mma.sync fp16 split (HMMA).
//   128 CTAs x 256 thr. Per step: gates[128 x 2048] = h @ W^T, N=16 rows/CTA.
//   fp16 3-term split with x2048-scaled lo operands (residual ~2^-22).
//   Flag-array grid barrier (parallel poll), decoder pred folded into the main
//   barrier via red.global.add partials, parallel split-K C reduction.
// ----------------------------------------------------------------------------

#define NCTA   128
#define NTHR   256
#define T_ENC  512
#define W_DEC  96
#define HID    512
#define BATCH  128
#define NG     16        // gate rows per CTA (4 H-cols x 4 gates)

#define SLOT_BYTES 32768          // hi 16KB + lo 16KB, SW128 swizzled 128B rows
#define WROW       1040           // W row stride bytes (512 fp16 + pad)
#define WHI_OFF    131072         // 4 slots * 32768
#define WLO_OFF    147712
#define CSM_OFF    164352         // f32 [2][128][17]
#define WIH_OFF    181760         // f32 [16][8]
#define BSM_OFF    182272         // f32 [16]
#define WXA_OFF    182336         // f32 [16]
#define WFC_OFF    182400         // f32 [512]
#define SMEM_TOTAL 184448

#define SWZ(x) ((x) ^ (((x) >> 3) & 0x70))

__device__ __half    g_hhi[2][BATCH][HID];
__device__ __half    g_hlo[2][BATCH][HID];
__device__ float     g_predsum[W_DEC][BATCH];
__device__ unsigned  g_flags[NCTA];

__device__ __forceinline__ float sigf(float x)     { return 1.f / (1.f + __expf(-x)); }
__device__ __forceinline__ float tanh_acc(float x) { return 1.f - 2.f / (1.f + __expf(2.f * x)); }

__device__ __forceinline__ uint32_t smem_u32_of(const void* p) {
    uint32_t a;
    asm("{ .reg .u64 t; cvta.to.shared.u64 t, %1; cvt.u32.u64 %0, t; }" : "=r"(a) : "l"(p));
    return a;
}
__device__ __forceinline__ float ldcg(const float* p) {
    float v; asm volatile("ld.global.cg.f32 %0, [%1];" : "=f"(v) : "l"(p)); return v;
}
__device__ __forceinline__ void stcg32(void* p, uint32_t v) {
    asm volatile("st.global.cg.b32 [%0], %1;" :: "l"(p), "r"(v));
}
__device__ __forceinline__ void redaddf(float* p, float v) {
    asm volatile("red.global.add.f32 [%0], %1;" :: "l"(p), "f"(v));
}
__device__ __forceinline__ void cp16(uint32_t dst, const void* src) {
    asm volatile("cp.async.cg.shared.global [%0], [%1], 16;" :: "r"(dst), "l"(src));
}
__device__ __forceinline__ void cp_commit() { asm volatile("cp.async.commit_group;"); }
template <int N> __device__ __forceinline__ void cp_wait() {
    asm volatile("cp.async.wait_group %0;" :: "n"(N));
}
__device__ __forceinline__ void ldsm4(uint32_t& r0, uint32_t& r1, uint32_t& r2, uint32_t& r3,
                                      uint32_t addr) {
    asm volatile("ldmatrix.sync.aligned.m8n8.x4.shared.b16 {%0,%1,%2,%3}, [%4];"
                 : "=r"(r0), "=r"(r1), "=r"(r2), "=r"(r3) : "r"(addr));
}
__device__ __forceinline__ void mma16816(float* c, uint32_t a0, uint32_t a1, uint32_t a2,
                                         uint32_t a3, uint32_t b0, uint32_t b1) {
    asm volatile("mma.sync.aligned.m16n8k16.row.col.f32.f16.f16.f32 "
                 "{%0,%1,%2,%3}, {%4,%5,%6,%7}, {%8,%9}, {%0,%1,%2,%3};"
                 : "+f"(c[0]), "+f"(c[1]), "+f"(c[2]), "+f"(c[3])
                 : "r"(a0), "r"(a1), "r"(a2), "r"(a3), "r"(b0), "r"(b1));
}

// Flag-array grid barrier: CTA posts its step-stamped flag; 128 threads poll
// all flags in parallel (4 cache lines), then block-sync.
__device__ __forceinline__ void gridbar(unsigned step1, int tid, int cta) {
    __syncthreads();
    __threadfence();
    if (tid == 0) {
        asm volatile("st.global.cg.u32 [%0], %1;" :: "l"(&g_flags[cta]), "r"(step1));
    }
    if (tid < NCTA) {
        unsigned cur;
        for (;;) {
            asm volatile("ld.global.cg.u32 %0, [%1];" : "=r"(cur) : "l"(&g_flags[tid]));
            if (cur >= step1) break;
            __nanosleep(32);
        }
    }
    __syncthreads();
}

// Stage chunk ck (64 fp16 cols of h hi+lo) into slot (SW128 swizzled rows).
__device__ __forceinline__ void stage_chunk(uint32_t smem_b, int slot, int ck, int p, int tid) {
    uint32_t base = smem_b + (uint32_t)slot * SLOT_BYTES;
    const char* shi = (const char*)&g_hhi[p][0][ck * 64];
    const char* slo = (const char*)&g_hlo[p][0][ck * 64];
    #pragma unroll
    for (int i = 0; i < 4; ++i) {
        int idx = i * NTHR + tid;             // 1024 16B pieces per plane
        int b = idx >> 3, j = idx & 7;
        uint32_t off = SWZ((uint32_t)(b * 128 + j * 16));
        cp16(base + off,          shi + (size_t)b * (HID * 2) + j * 16);
        cp16(base + 16384u + off, slo + (size_t)b * (HID * 2) + j * 16);
    }
}

// W slice (16 gate-rows x 512) -> fp16 hi + (lo*2048), padded rows.
__device__ __forceinline__ void load_W(const float* __restrict__ Whh, char* sm, int cta, int tid) {
    for (int idx = tid; idx < NG * HID; idx += NTHR) {
        int n = idx >> 9, k = idx & 511;
        int c = n >> 2, g = n & 3;
        int row = g * HID + cta * 4 + c;
        float w = Whh[(size_t)row * HID + k];
        __half whi = __float2half(w);
        __half wlo = __float2half((w - __half2float(whi)) * 2048.f);
        *(__half*)(sm + WHI_OFF + n * WROW + k * 2) = whi;
        *(__half*)(sm + WLO_OFF + n * WROW + k * 2) = wlo;
    }
}

__global__ void init_kernel() {
    size_t i = (size_t)blockIdx.x * blockDim.x + threadIdx.x;
    size_t stride = (size_t)gridDim.x * blockDim.x;
    uint32_t* hh = (uint32_t*)&g_hhi[0][0][0];
    uint32_t* hl = (uint32_t*)&g_hlo[0][0][0];
    size_t n = 2ull * BATCH * HID / 2;
    for (size_t k = i; k < n; k += stride) { hh[k] = 0u; hl[k] = 0u; }
    float* ps = &g_predsum[0][0];
    for (size_t k = i; k < (size_t)W_DEC * BATCH; k += stride) ps[k] = 0.f;
    if (i < NCTA) g_flags[i] = 0u;
}

__global__ void __launch_bounds__(NTHR, 1)
fore_kernel(const float* __restrict__ src,
            const float* __restrict__ Wih_e, const float* __restrict__ Whh_e,
            const float* __restrict__ bih_e, const float* __restrict__ bhh_e,
            const float* __restrict__ Wih_d, const float* __restrict__ Whh_d,
            const float* __restrict__ bih_d, const float* __restrict__ bhh_d,
            const float* __restrict__ Wp,    const float* __restrict__ bp,
            const float* __restrict__ Wfc,   const float* __restrict__ bfc,
            float* __restrict__ out)
{
    extern __shared__ char sm[];
    const uint32_t smem_b = smem_u32_of(sm);
    float* Csm    = (float*)(sm + CSM_OFF);        // [2][128][17]
    float* wih_sm = (float*)(sm + WIH_OFF);
    float* bsm    = (float*)(sm + BSM_OFF);
    float* wxa    = (float*)(sm + WXA_OFF);
    float* wfc_sm = (float*)(sm + WFC_OFF);

    const int tid  = threadIdx.x;
    const int cta  = blockIdx.x;
    const int wid  = tid >> 5;
    const int lane = tid & 31;
    const int kg   = wid >> 2;            // K group (0: K[0,256), 1: K[256,512))
    const int wm   = wid & 3;             // warp's M block (32 rows)
    const int eb   = tid >> 1;            // epilogue batch
    const int half = tid & 1;             // epilogue col half (2 cols)

    // ldmatrix lane addressing
    const int a_row  = (lane & 7) + ((lane >> 3) & 1) * 8;
    const int a_bcol = ((lane >> 4) & 1) * 16;
    const uint32_t b_off = (uint32_t)(((lane & 7) + ((lane >> 4) & 1) * 8) * WROW
                                      + ((lane >> 3) & 1) * 16);

    const float bfcv = __ldg(bfc);

    // ---- encoder weights ----
    load_W(Whh_e, sm, cta, tid);
    if (tid < NG * 8) {
        int n = tid >> 3, i = tid & 7;
        int c = n >> 2, g = n & 3;
        int row = g * HID + cta * 4 + c;
        wih_sm[n * 8 + i] = Wih_e[row * 8 + i];
    }
    if (tid < NG) {
        int c = tid >> 2, g = tid & 3;
        int row = g * HID + cta * 4 + c;
        bsm[tid] = bih_e[row] + bhh_e[row];
    }
    for (int k = tid; k < HID; k += NTHR) wfc_sm[k] = Wfc[k];
    __syncthreads();

    float cc[2] = {0.f, 0.f};
    int p = 0;

    for (int step = 0; step < T_ENC + W_DEC; ++step) {
        const bool enc = (step < T_ENC);
        const int  t   = enc ? step : step - T_ENC;

        if (step == T_ENC) {                      // decoder weight swap
            load_W(Whh_d, sm, cta, tid);
            __syncthreads();
            if (tid < NG) {
                int c = tid >> 2, g = tid & 3;
                int row = g * HID + cta * 4 + c;
                float A = 0.f, B0 = 0.f;
                #pragma unroll
                for (int i = 0; i < 8; ++i) {
                    float wih = Wih_d[row * 8 + i];
                    A  += Wp[i] * wih;
                    B0 += bp[i] * wih;
                }
                bsm[tid] = bih_d[row] + bhh_d[row] + B0;
                wxa[tid] = A;
            }
            __syncthreads();
        }

        // output write for decoder step t-1 (predsum complete after prev barrier)
        if (!enc && t >= 1 && tid == 0) {
            out[cta * W_DEC + (t - 1)] = sigf(ldcg(&g_predsum[t - 1][cta]) + bfcv);
        }

        // =================== step GEMM ===================
        float accA[2][2][4], accB[2][2][4];
        #pragma unroll
        for (int i = 0; i < 2; ++i)
            #pragma unroll
            for (int j = 0; j < 2; ++j)
                #pragma unroll
                for (int q = 0; q < 4; ++q) { accA[i][j][q] = 0.f; accB[i][j][q] = 0.f; }

        stage_chunk(smem_b, 0, 0, p, tid);
        stage_chunk(smem_b, 2, 4, p, tid);
        cp_commit();

        #pragma unroll
        for (int i = 0; i < 4; ++i) {
            cp_wait<0>();
            __syncthreads();                      // chunks ready; prior slot reads done
            if (i < 3) {                          // prefetch next pair
                stage_chunk(smem_b, (i + 1) & 1,       i + 1, p, tid);
                stage_chunk(smem_b, 2 + ((i + 1) & 1), i + 5, p, tid);
                cp_commit();
            }
            const int ck = kg * 4 + i;
            const uint32_t sA  = smem_b + (uint32_t)(2 * kg + (i & 1)) * SLOT_BYTES;
            const uint32_t wB  = smem_b + (uint32_t)(ck * 128) + b_off;

            #pragma unroll
            for (int k16 = 0; k16 < 4; ++k16) {
                const int bc = a_bcol + k16 * 32;
                uint32_t Ah[2][4], Al[2][4], Bh[4], Bl[4];
                #pragma unroll
                for (int mt = 0; mt < 2; ++mt) {
                    uint32_t ra = sA + SWZ((uint32_t)((wm * 32 + mt * 16 + a_row) * 128 + bc));
                    ldsm4(Ah[mt][0], Ah[mt][1], Ah[mt][2], Ah[mt][3], ra);
                    ldsm4(Al[mt][0], Al[mt][1], Al[mt][2], Al[mt][3], ra + 16384u);
                }
                ldsm4(Bh[0], Bh[1], Bh[2], Bh[3], wB + WHI_OFF + k16 * 32);
                ldsm4(Bl[0], Bl[1], Bl[2], Bl[3], wB + WLO_OFF + k16 * 32);

                #pragma unroll
                for (int mt = 0; mt < 2; ++mt) {
                    #pragma unroll
                    for (int nt = 0; nt < 2; ++nt) {
                        uint32_t bh0 = Bh[nt * 2], bh1 = Bh[nt * 2 + 1];
                        uint32_t bl0 = Bl[nt * 2], bl1 = Bl[nt * 2 + 1];
                        mma16816(accA[mt][nt], Ah[mt][0], Ah[mt][1], Ah[mt][2], Ah[mt][3], bh0, bh1);
                        mma16816(accB[mt][nt], Al[mt][0], Al[mt][1], Al[mt][2], Al[mt][3], bh0, bh1);
                        mma16816(accB[mt][nt], Ah[mt][0], Ah[mt][1], Ah[mt][2], Ah[mt][3], bl0, bl1);
                    }
                }
            }
        }

        // C write: each K-group to its own buffer (parallel), one sync
        {
            float* Cme = Csm + kg * (BATCH * 17);
            #pragma unroll
            for (int mt = 0; mt < 2; ++mt) {
                int r = wm * 32 + mt * 16 + (lane >> 2);
                #pragma unroll
                for (int nt = 0; nt < 2; ++nt) {
                    int cb = nt * 8 + (lane & 3) * 2;
                    Cme[r * 17 + cb]           = accA[mt][nt][0] + accB[mt][nt][0] * (1.f / 2048.f);
                    Cme[r * 17 + cb + 1]       = accA[mt][nt][1] + accB[mt][nt][1] * (1.f / 2048.f);
                    Cme[(r + 8) * 17 + cb]     = accA[mt][nt][2] + accB[mt][nt][2] * (1.f / 2048.f);
                    Cme[(r + 8) * 17 + cb + 1] = accA[mt][nt][3] + accB[mt][nt][3] * (1.f / 2048.f);
                }
            }
        }
        __syncthreads();

        // =================== LSTM epilogue: thread = (batch, col-half) =========
        float xg8[8];
        float xv = 0.f;
        if (enc) {
            const float* sp = src + ((size_t)eb * T_ENC + t) * 8;
            float4 sa = *(const float4*)sp;
            float4 sb4 = *(const float4*)(sp + 4);
            xg8[0] = sa.x;  xg8[1] = sa.y;  xg8[2] = sa.z;  xg8[3] = sa.w;
            xg8[4] = sb4.x; xg8[5] = sb4.y; xg8[6] = sb4.z; xg8[7] = sb4.w;
        } else {
            xv = (t == 0) ? __ldg(&src[((size_t)eb * T_ENC + (T_ENC - 1)) * 8])
                          : sigf(ldcg(&g_predsum[t - 1][eb]) + bfcv);
        }

        uint32_t packh = 0, packl = 0;
        float part = 0.f;
        #pragma unroll
        for (int ci = 0; ci < 2; ++ci) {
            int nb = (half * 2 + ci) * 4;
            float gate[4];
            #pragma unroll
            for (int g = 0; g < 4; ++g) {
                int n = nb + g;
                float xpart;
                if (enc) {
                    const float* wr = wih_sm + n * 8;
                    xpart = xg8[0]*wr[0] + xg8[1]*wr[1] + xg8[2]*wr[2] + xg8[3]*wr[3]
                          + xg8[4]*wr[4] + xg8[5]*wr[5] + xg8[6]*wr[6] + xg8[7]*wr[7];
                } else {
                    xpart = xv * wxa[n];
                }
                gate[g] = Csm[eb * 17 + n] + Csm[BATCH * 17 + eb * 17 + n] + xpart + bsm[n];
            }
            float ig = sigf(gate[0]), fg = sigf(gate[1]);
            float gg = tanh_acc(gate[2]), og = sigf(gate[3]);
            float cn = fg * cc[ci] + ig * gg;
            float hn = og * tanh_acc(cn);
            cc[ci] = cn;
            __half hh = __float2half(hn);
            __half hl = __float2half((hn - __half2float(hh)) * 2048.f);
            packh |= (uint32_t)__half_as_ushort(hh) << (ci * 16);
            packl |= (uint32_t)__half_as_ushort(hl) << (ci * 16);
            if (!enc) part = fmaf(hn, wfc_sm[cta * 4 + half * 2 + ci], part);
        }
        stcg32(&g_hhi[p ^ 1][eb][cta * 4 + half * 2], packh);
        stcg32(&g_hlo[p ^ 1][eb][cta * 4 + half * 2], packl);
        if (!enc) redaddf(&g_predsum[t][eb], part);   // pred partial (fp32 h)

        gridbar((unsigned)(step + 1), tid, cta);
        p ^= 1;
    }

    // final decoder output (predsum[95] complete after final barrier)
    if (tid == 0) {
        out[cta * W_DEC + (W_DEC - 1)] = sigf(ldcg(&g_predsum[W_DEC - 1][cta]) + bfcv);
    }
}

extern "C" void kernel_launch(void* const* d_in, const int* in_sizes, int n_in,
                              void* d_out, int out_size) {
    const float* src   = (const float*)d_in[0];
    const float* Wih_e = (const float*)d_in[1];
    const float* Whh_e = (const float*)d_in[2];
    const float* bih_e = (const float*)d_in[3];
    const float* bhh_e = (const float*)d_in[4];
    const float* Wih_d = (const float*)d_in[5];
    const float* Whh_d = (const float*)d_in[6];
    const float* bih_d = (const float*)d_in[7];
    const float* bhh_d = (const float*)d_in[8];
    const float* Wp    = (const float*)d_in[9];
    const float* bp    = (const float*)d_in[10];
    const float* Wfc   = (const float*)d_in[11];
    const float* bfc   = (const float*)d_in[12];
    float* out = (float*)d_out;

    cudaFuncSetAttribute(fore_kernel, cudaFuncAttributeMaxDynamicSharedMemorySize, SMEM_TOTAL);

    init_kernel<<<64, 256>>>();
    fore_kernel<<<NCTA, NTHR, SMEM_TOTAL>>>(src, Wih_e, Whh_e, bih_e, bhh_e,
                                            Wih_d, Whh_d, bih_d, bhh_d,
                                            Wp, bp, Wfc, bfc, out);
}

// round 16
// speedup vs baseline: 2.2162x; 2.2162x over previous
#include <cuda_runtime.h>
#include <cuda_fp16.h>
#include <cstdint>
#include <cstddef>

// ----------------------------------------------------------------------------
// ForecastNetSimple via mma.sync fp16 split (HMMA).
//   128 CTAs x 256 thr. Per step: gates[128 x 2048] = h @ W^T, N=16 rows/CTA.
//   fp16 3-term split with x2048-scaled lo operands (residual ~2^-22).
//   R13: hierarchical grid barrier — red.global.add arrival into 8 group
//   counters (16 CTAs each, separate 128B lines) + ONE observer thread per CTA
//   polling the 8 counters. (R12's 128-observer flag barrier regressed 2x:
//   worst-of-128 poll wakeups + 512 polling warps on 4 lines.)
//   Decoder pred fused into the barrier via red.global.add partials; parallel
//   split-K C reduction.
// ----------------------------------------------------------------------------

#define NCTA   128
#define NTHR   256
#define T_ENC  512
#define W_DEC  96
#define HID    512
#define BATCH  128
#define NG     16        // gate rows per CTA (4 H-cols x 4 gates)
#define NGRP   8         // barrier groups (16 CTAs each)

#define SLOT_BYTES 32768          // hi 16KB + lo 16KB, SW128 swizzled 128B rows
#define WROW       1040           // W row stride bytes (512 fp16 + pad)
#define WHI_OFF    131072         // 4 slots * 32768
#define WLO_OFF    147712
#define CSM_OFF    164352         // f32 [2][128][17]
#define WIH_OFF    181760         // f32 [16][8]
#define BSM_OFF    182272         // f32 [16]
#define WXA_OFF    182336         // f32 [16]
#define WFC_OFF    182400         // f32 [512]
#define SMEM_TOTAL 184448

#define SWZ(x) ((x) ^ (((x) >> 3) & 0x70))

__device__ __half    g_hhi[2][BATCH][HID];
__device__ __half    g_hlo[2][BATCH][HID];
__device__ float     g_predsum[W_DEC][BATCH];
__device__ unsigned  g_barg[NGRP * 32];   // group counters, one per 128B line

__device__ __forceinline__ float sigf(float x)     { return 1.f / (1.f + __expf(-x)); }
__device__ __forceinline__ float tanh_acc(float x) { return 1.f - 2.f / (1.f + __expf(2.f * x)); }

__device__ __forceinline__ uint32_t smem_u32_of(const void* p) {
    uint32_t a;
    asm("{ .reg .u64 t; cvta.to.shared.u64 t, %1; cvt.u32.u64 %0, t; }" : "=r"(a) : "l"(p));
    return a;
}
__device__ __forceinline__ float ldcg(const float* p) {
    float v; asm volatile("ld.global.cg.f32 %0, [%1];" : "=f"(v) : "l"(p)); return v;
}
__device__ __forceinline__ unsigned ldcgu(const unsigned* p) {
    unsigned v; asm volatile("ld.global.cg.u32 %0, [%1];" : "=r"(v) : "l"(p)); return v;
}
__device__ __forceinline__ void stcg32(void* p, uint32_t v) {
    asm volatile("st.global.cg.b32 [%0], %1;" :: "l"(p), "r"(v));
}
__device__ __forceinline__ void redaddf(float* p, float v) {
    asm volatile("red.global.add.f32 [%0], %1;" :: "l"(p), "f"(v));
}
__device__ __forceinline__ void redaddu(unsigned* p, unsigned v) {
    asm volatile("red.global.add.u32 [%0], %1;" :: "l"(p), "r"(v));
}
__device__ __forceinline__ void cp16(uint32_t dst, const void* src) {
    asm volatile("cp.async.cg.shared.global [%0], [%1], 16;" :: "r"(dst), "l"(src));
}
__device__ __forceinline__ void cp_commit() { asm volatile("cp.async.commit_group;"); }
template <int N> __device__ __forceinline__ void cp_wait() {
    asm volatile("cp.async.wait_group %0;" :: "n"(N));
}
__device__ __forceinline__ void ldsm4(uint32_t& r0, uint32_t& r1, uint32_t& r2, uint32_t& r3,
                                      uint32_t addr) {
    asm volatile("ldmatrix.sync.aligned.m8n8.x4.shared.b16 {%0,%1,%2,%3}, [%4];"
                 : "=r"(r0), "=r"(r1), "=r"(r2), "=r"(r3) : "r"(addr));
}
__device__ __forceinline__ void mma16816(float* c, uint32_t a0, uint32_t a1, uint32_t a2,
                                         uint32_t a3, uint32_t b0, uint32_t b1) {
    asm volatile("mma.sync.aligned.m16n8k16.row.col.f32.f16.f16.f32 "
                 "{%0,%1,%2,%3}, {%4,%5,%6,%7}, {%8,%9}, {%0,%1,%2,%3};"
                 : "+f"(c[0]), "+f"(c[1]), "+f"(c[2]), "+f"(c[3])
                 : "r"(a0), "r"(a1), "r"(a2), "r"(a3), "r"(b0), "r"(b1));
}

// Hierarchical grid barrier: no-return red.add arrival into 8 group counters;
// single observer thread polls the 8 counters (pipelined independent loads).
__device__ __forceinline__ void gridbar(unsigned step1, int tid, int cta) {
    __syncthreads();
    __threadfence();
    if (tid == 0) {
        redaddu(&g_barg[(cta >> 4) * 32], 1u);
        const unsigned tgt = step1 * 16u;
        for (;;) {
            unsigned c0 = ldcgu(&g_barg[0 * 32]);
            unsigned c1 = ldcgu(&g_barg[1 * 32]);
            unsigned c2 = ldcgu(&g_barg[2 * 32]);
            unsigned c3 = ldcgu(&g_barg[3 * 32]);
            unsigned c4 = ldcgu(&g_barg[4 * 32]);
            unsigned c5 = ldcgu(&g_barg[5 * 32]);
            unsigned c6 = ldcgu(&g_barg[6 * 32]);
            unsigned c7 = ldcgu(&g_barg[7 * 32]);
            if (c0 >= tgt && c1 >= tgt && c2 >= tgt && c3 >= tgt &&
                c4 >= tgt && c5 >= tgt && c6 >= tgt && c7 >= tgt) break;
            __nanosleep(20);
        }
    }
    __syncthreads();
}

// Stage chunk ck (64 fp16 cols of h hi+lo) into slot (SW128 swizzled rows).
__device__ __forceinline__ void stage_chunk(uint32_t smem_b, int slot, int ck, int p, int tid) {
    uint32_t base = smem_b + (uint32_t)slot * SLOT_BYTES;
    const char* shi = (const char*)&g_hhi[p][0][ck * 64];
    const char* slo = (const char*)&g_hlo[p][0][ck * 64];
    #pragma unroll
    for (int i = 0; i < 4; ++i) {
        int idx = i * NTHR + tid;             // 1024 16B pieces per plane
        int b = idx >> 3, j = idx & 7;
        uint32_t off = SWZ((uint32_t)(b * 128 + j * 16));
        cp16(base + off,          shi + (size_t)b * (HID * 2) + j * 16);
        cp16(base + 16384u + off, slo + (size_t)b * (HID * 2) + j * 16);
    }
}

// W slice (16 gate-rows x 512) -> fp16 hi + (lo*2048), padded rows.
__device__ __forceinline__ void load_W(const float* __restrict__ Whh, char* sm, int cta, int tid) {
    for (int idx = tid; idx < NG * HID; idx += NTHR) {
        int n = idx >> 9, k = idx & 511;
        int c = n >> 2, g = n & 3;
        int row = g * HID + cta * 4 + c;
        float w = Whh[(size_t)row * HID + k];
        __half whi = __float2half(w);
        __half wlo = __float2half((w - __half2float(whi)) * 2048.f);
        *(__half*)(sm + WHI_OFF + n * WROW + k * 2) = whi;
        *(__half*)(sm + WLO_OFF + n * WROW + k * 2) = wlo;
    }
}

__global__ void init_kernel() {
    size_t i = (size_t)blockIdx.x * blockDim.x + threadIdx.x;
    size_t stride = (size_t)gridDim.x * blockDim.x;
    uint32_t* hh = (uint32_t*)&g_hhi[0][0][0];
    uint32_t* hl = (uint32_t*)&g_hlo[0][0][0];
    size_t n = 2ull * BATCH * HID / 2;
    for (size_t k = i; k < n; k += stride) { hh[k] = 0u; hl[k] = 0u; }
    float* ps = &g_predsum[0][0];
    for (size_t k = i; k < (size_t)W_DEC * BATCH; k += stride) ps[k] = 0.f;
    if (i < NGRP * 32) g_barg[i] = 0u;
}

__global__ void __launch_bounds__(NTHR, 1)
fore_kernel(const float* __restrict__ src,
            const float* __restrict__ Wih_e, const float* __restrict__ Whh_e,
            const float* __restrict__ bih_e, const float* __restrict__ bhh_e,
            const float* __restrict__ Wih_d, const float* __restrict__ Whh_d,
            const float* __restrict__ bih_d, const float* __restrict__ bhh_d,
            const float* __restrict__ Wp,    const float* __restrict__ bp,
            const float* __restrict__ Wfc,   const float* __restrict__ bfc,
            float* __restrict__ out)
{
    extern __shared__ char sm[];
    const uint32_t smem_b = smem_u32_of(sm);
    float* Csm    = (float*)(sm + CSM_OFF);        // [2][128][17]
    float* wih_sm = (float*)(sm + WIH_OFF);
    float* bsm    = (float*)(sm + BSM_OFF);
    float* wxa    = (float*)(sm + WXA_OFF);
    float* wfc_sm = (float*)(sm + WFC_OFF);

    const int tid  = threadIdx.x;
    const int cta  = blockIdx.x;
    const int wid  = tid >> 5;
    const int lane = tid & 31;
    const int kg   = wid >> 2;            // K group (0: K[0,256), 1: K[256,512))
    const int wm   = wid & 3;             // warp's M block (32 rows)
    const int eb   = tid >> 1;            // epilogue batch
    const int half = tid & 1;             // epilogue col half (2 cols)

    // ldmatrix lane addressing
    const int a_row  = (lane & 7) + ((lane >> 3) & 1) * 8;
    const int a_bcol = ((lane >> 4) & 1) * 16;
    const uint32_t b_off = (uint32_t)(((lane & 7) + ((lane >> 4) & 1) * 8) * WROW
                                      + ((lane >> 3) & 1) * 16);

    const float bfcv = __ldg(bfc);

    // ---- encoder weights ----
    load_W(Whh_e, sm, cta, tid);
    if (tid < NG * 8) {
        int n = tid >> 3, i = tid & 7;
        int c = n >> 2, g = n & 3;
        int row = g * HID + cta * 4 + c;
        wih_sm[n * 8 + i] = Wih_e[row * 8 + i];
    }
    if (tid < NG) {
        int c = tid >> 2, g = tid & 3;
        int row = g * HID + cta * 4 + c;
        bsm[tid] = bih_e[row] + bhh_e[row];
    }
    for (int k = tid; k < HID; k += NTHR) wfc_sm[k] = Wfc[k];
    __syncthreads();

    float cc[2] = {0.f, 0.f};
    int p = 0;

    for (int step = 0; step < T_ENC + W_DEC; ++step) {
        const bool enc = (step < T_ENC);
        const int  t   = enc ? step : step - T_ENC;

        if (step == T_ENC) {                      // decoder weight swap
            load_W(Whh_d, sm, cta, tid);
            __syncthreads();
            if (tid < NG) {
                int c = tid >> 2, g = tid & 3;
                int row = g * HID + cta * 4 + c;
                float A = 0.f, B0 = 0.f;
                #pragma unroll
                for (int i = 0; i < 8; ++i) {
                    float wih = Wih_d[row * 8 + i];
                    A  += Wp[i] * wih;
                    B0 += bp[i] * wih;
                }
                bsm[tid] = bih_d[row] + bhh_d[row] + B0;
                wxa[tid] = A;
            }
            __syncthreads();
        }

        // output write for decoder step t-1 (predsum complete after prev barrier)
        if (!enc && t >= 1 && tid == 0) {
            out[cta * W_DEC + (t - 1)] = sigf(ldcg(&g_predsum[t - 1][cta]) + bfcv);
        }

        // =================== step GEMM ===================
        float accA[2][2][4], accB[2][2][4];
        #pragma unroll
        for (int i = 0; i < 2; ++i)
            #pragma unroll
            for (int j = 0; j < 2; ++j)
                #pragma unroll
                for (int q = 0; q < 4; ++q) { accA[i][j][q] = 0.f; accB[i][j][q] = 0.f; }

        stage_chunk(smem_b, 0, 0, p, tid);
        stage_chunk(smem_b, 2, 4, p, tid);
        cp_commit();

        #pragma unroll
        for (int i = 0; i < 4; ++i) {
            cp_wait<0>();
            __syncthreads();                      // chunks ready; prior slot reads done
            if (i < 3) {                          // prefetch next pair
                stage_chunk(smem_b, (i + 1) & 1,       i + 1, p, tid);
                stage_chunk(smem_b, 2 + ((i + 1) & 1), i + 5, p, tid);
                cp_commit();
            }
            const int ck = kg * 4 + i;
            const uint32_t sA  = smem_b + (uint32_t)(2 * kg + (i & 1)) * SLOT_BYTES;
            const uint32_t wB  = smem_b + (uint32_t)(ck * 128) + b_off;

            #pragma unroll
            for (int k16 = 0; k16 < 4; ++k16) {
                const int bc = a_bcol + k16 * 32;
                uint32_t Ah[2][4], Al[2][4], Bh[4], Bl[4];
                #pragma unroll
                for (int mt = 0; mt < 2; ++mt) {
                    uint32_t ra = sA + SWZ((uint32_t)((wm * 32 + mt * 16 + a_row) * 128 + bc));
                    ldsm4(Ah[mt][0], Ah[mt][1], Ah[mt][2], Ah[mt][3], ra);
                    ldsm4(Al[mt][0], Al[mt][1], Al[mt][2], Al[mt][3], ra + 16384u);
                }
                ldsm4(Bh[0], Bh[1], Bh[2], Bh[3], wB + WHI_OFF + k16 * 32);
                ldsm4(Bl[0], Bl[1], Bl[2], Bl[3], wB + WLO_OFF + k16 * 32);

                #pragma unroll
                for (int mt = 0; mt < 2; ++mt) {
                    #pragma unroll
                    for (int nt = 0; nt < 2; ++nt) {
                        uint32_t bh0 = Bh[nt * 2], bh1 = Bh[nt * 2 + 1];
                        uint32_t bl0 = Bl[nt * 2], bl1 = Bl[nt * 2 + 1];
                        mma16816(accA[mt][nt], Ah[mt][0], Ah[mt][1], Ah[mt][2], Ah[mt][3], bh0, bh1);
                        mma16816(accB[mt][nt], Al[mt][0], Al[mt][1], Al[mt][2], Al[mt][3], bh0, bh1);
                        mma16816(accB[mt][nt], Ah[mt][0], Ah[mt][1], Ah[mt][2], Ah[mt][3], bl0, bl1);
                    }
                }
            }
        }

        // C write: each K-group to its own buffer (parallel), one sync
        {
            float* Cme = Csm + kg * (BATCH * 17);
            #pragma unroll
            for (int mt = 0; mt < 2; ++mt) {
                int r = wm * 32 + mt * 16 + (lane >> 2);
                #pragma unroll
                for (int nt = 0; nt < 2; ++nt) {
                    int cb = nt * 8 + (lane & 3) * 2;
                    Cme[r * 17 + cb]           = accA[mt][nt][0] + accB[mt][nt][0] * (1.f / 2048.f);
                    Cme[r * 17 + cb + 1]       = accA[mt][nt][1] + accB[mt][nt][1] * (1.f / 2048.f);
                    Cme[(r + 8) * 17 + cb]     = accA[mt][nt][2] + accB[mt][nt][2] * (1.f / 2048.f);
                    Cme[(r + 8) * 17 + cb + 1] = accA[mt][nt][3] + accB[mt][nt][3] * (1.f / 2048.f);
                }
            }
        }
        __syncthreads();

        // =================== LSTM epilogue: thread = (batch, col-half) =========
        float xg8[8];
        float xv = 0.f;
        if (enc) {
            const float* sp = src + ((size_t)eb * T_ENC + t) * 8;
            float4 sa = *(const float4*)sp;
            float4 sb4 = *(const float4*)(sp + 4);
            xg8[0] = sa.x;  xg8[1] = sa.y;  xg8[2] = sa.z;  xg8[3] = sa.w;
            xg8[4] = sb4.x; xg8[5] = sb4.y; xg8[6] = sb4.z; xg8[7] = sb4.w;
        } else {
            xv = (t == 0) ? __ldg(&src[((size_t)eb * T_ENC + (T_ENC - 1)) * 8])
                          : sigf(ldcg(&g_predsum[t - 1][eb]) + bfcv);
        }

        uint32_t packh = 0, packl = 0;
        float part = 0.f;
        #pragma unroll
        for (int ci = 0; ci < 2; ++ci) {
            int nb = (half * 2 + ci) * 4;
            float gate[4];
            #pragma unroll
            for (int g = 0; g < 4; ++g) {
                int n = nb + g;
                float xpart;
                if (enc) {
                    const float* wr = wih_sm + n * 8;
                    xpart = xg8[0]*wr[0] + xg8[1]*wr[1] + xg8[2]*wr[2] + xg8[3]*wr[3]
                          + xg8[4]*wr[4] + xg8[5]*wr[5] + xg8[6]*wr[6] + xg8[7]*wr[7];
                } else {
                    xpart = xv * wxa[n];
                }
                gate[g] = Csm[eb * 17 + n] + Csm[BATCH * 17 + eb * 17 + n] + xpart + bsm[n];
            }
            float ig = sigf(gate[0]), fg = sigf(gate[1]);
            float gg = tanh_acc(gate[2]), og = sigf(gate[3]);
            float cn = fg * cc[ci] + ig * gg;
            float hn = og * tanh_acc(cn);
            cc[ci] = cn;
            __half hh = __float2half(hn);
            __half hl = __float2half((hn - __half2float(hh)) * 2048.f);
            packh |= (uint32_t)__half_as_ushort(hh) << (ci * 16);
            packl |= (uint32_t)__half_as_ushort(hl) << (ci * 16);
            if (!enc) part = fmaf(hn, wfc_sm[cta * 4 + half * 2 + ci], part);
        }
        stcg32(&g_hhi[p ^ 1][eb][cta * 4 + half * 2], packh);
        stcg32(&g_hlo[p ^ 1][eb][cta * 4 + half * 2], packl);
        if (!enc) redaddf(&g_predsum[t][eb], part);   // pred partial (fp32 h)

        gridbar((unsigned)(step + 1), tid, cta);
        p ^= 1;
    }

    // final decoder output (predsum[95] complete after final barrier)
    if (tid == 0) {
        out[cta * W_DEC + (W_DEC - 1)] = sigf(ldcg(&g_predsum[W_DEC - 1][cta]) + bfcv);
    }
}

extern "C" void kernel_launch(void* const* d_in, const int* in_sizes, int n_in,
                              void* d_out, int out_size) {
    const float* src   = (const float*)d_in[0];
    const float* Wih_e = (const float*)d_in[1];
    const float* Whh_e = (const float*)d_in[2];
    const float* bih_e = (const float*)d_in[3];
    const float* bhh_e = (const float*)d_in[4];
    const float* Wih_d = (const float*)d_in[5];
    const float* Whh_d = (const float*)d_in[6];
    const float* bih_d = (const float*)d_in[7];
    const float* bhh_d = (const float*)d_in[8];
    const float* Wp    = (const float*)d_in[9];
    const float* bp    = (const float*)d_in[10];
    const float* Wfc   = (const float*)d_in[11];
    const float* bfc   = (const float*)d_in[12];
    float* out = (float*)d_out;

    cudaFuncSetAttribute(fore_kernel, cudaFuncAttributeMaxDynamicSharedMemorySize, SMEM_TOTAL);

    init_kernel<<<64, 256>>>();
    fore_kernel<<<NCTA, NTHR, SMEM_TOTAL>>>(src, Wih_e, Whh_e, bih_e, bhh_e,
                                            Wih_d, Whh_d, bih_d, bhh_d,
                                            Wp, bp, Wfc, bfc, out);
}